// round 1
// baseline (speedup 1.0000x reference)
#include <cuda_runtime.h>

#define BB 2
#define CIN 256
#define OCH 256
#define HH 48
#define WW 48
#define HP 54
#define WP 54
#define NPOS (HP*WP)      // 2916
#define KS 7
#define KK 49
#define ND2 85            // symmetric offsets: dr=0,dc>=0 (7) + dr in [1,6] x dc in [-6,6] (78)

// Scratch (device globals: no allocation allowed)
__device__ float g_QK[BB*NPOS*OCH];      // [b][p][o]   ~6.0 MB
__device__ float g_V [BB*NPOS*OCH];      // [b][p][o]   ~6.0 MB
__device__ float g_CORR[BB*NPOS*ND2];    // [b][p][d]   ~2.0 MB
__device__ float g_AB[BB*NPOS*16];       // [b][p][0..6]=A(rel_h), [8..14]=B(rel_w)

// ---------------------------------------------------------------------------
// Kernel 0: zero-fill QK and V (border positions stay zero; GEMM fills interior)
__global__ void kZero() {
    int tot4 = (BB*NPOS*OCH) / 4;
    float4 z = make_float4(0.f, 0.f, 0.f, 0.f);
    float4* q4 = (float4*)g_QK;
    float4* v4 = (float4*)g_V;
    for (int i = blockIdx.x*blockDim.x + threadIdx.x; i < tot4; i += gridDim.x*blockDim.x) {
        q4[i] = z; v4[i] = z;
    }
}

// ---------------------------------------------------------------------------
// Kernel 1: fused 1x1 conv GEMM.  C[n, m] = sum_c x[b,c,s(n)] * W[m, c]
// n = 4608 interior positions (b,h,w), m = 512 (0..255 -> w_key, 256..511 -> w_value)
// 128x128 tile, 256 threads, 8x8 micro-tiles (split 4+4 at +64 for conflict-free smem)
__global__ void kGemm(const float* __restrict__ x,
                      const float* __restrict__ wk,
                      const float* __restrict__ wv) {
    __shared__ float As[16][132];
    __shared__ float Bs[16][132];
    int tid = threadIdx.x;
    int n0 = blockIdx.x * 128;
    int m0 = blockIdx.y * 128;
    int tx = tid & 15, ty = tid >> 4;
    float acc[8][8];
    #pragma unroll
    for (int i = 0; i < 8; i++)
        #pragma unroll
        for (int j = 0; j < 8; j++) acc[i][j] = 0.f;

    for (int kt = 0; kt < 256; kt += 16) {
        #pragma unroll
        for (int i = 0; i < 8; i++) {           // As: 16k x 128n of x
            int flat = i*256 + tid;
            int k = flat >> 7, n = flat & 127;
            int nn = n0 + n;
            int b = nn / 2304, s = nn % 2304;   // tiles never straddle b (2304 % 128 == 0)
            As[k][n] = x[(b*256 + kt + k)*2304 + s];
        }
        #pragma unroll
        for (int i = 0; i < 8; i++) {           // Bs: 16k x 128m of weights
            int flat = i*256 + tid;
            int k = flat & 15, m = flat >> 4;
            int mm = m0 + m;
            Bs[k][m] = (mm < 256) ? wk[mm*256 + kt + k] : wv[(mm-256)*256 + kt + k];
        }
        __syncthreads();
        #pragma unroll
        for (int k = 0; k < 16; k++) {
            float a[8], bb[8];
            *(float4*)&a[0]  = *(float4*)&As[k][ty*4];
            *(float4*)&a[4]  = *(float4*)&As[k][64 + ty*4];
            *(float4*)&bb[0] = *(float4*)&Bs[k][tx*4];
            *(float4*)&bb[4] = *(float4*)&Bs[k][64 + tx*4];
            #pragma unroll
            for (int i = 0; i < 8; i++)
                #pragma unroll
                for (int j = 0; j < 8; j++)
                    acc[i][j] += a[i] * bb[j];
        }
        __syncthreads();
    }
    // epilogue: write QK / V at padded position (h+3, w+3), channel-contiguous
    #pragma unroll
    for (int i = 0; i < 8; i++) {
        int n = n0 + ((i < 4) ? (ty*4 + i) : (64 + ty*4 + i - 4));
        int b = n / 2304, rem = n % 2304;
        int h = rem / 48, w = rem % 48;
        int pidx = (h + 3)*54 + (w + 3);
        long rowq = (long)(b*NPOS + pidx)*256;
        #pragma unroll
        for (int jh = 0; jh < 2; jh++) {
            int m = m0 + ((jh == 0) ? tx*4 : 64 + tx*4);
            float4 v4 = make_float4(acc[i][jh*4+0], acc[i][jh*4+1], acc[i][jh*4+2], acc[i][jh*4+3]);
            if (m < 256) *(float4*)&g_QK[rowq + m]        = v4;
            else         *(float4*)&g_V [rowq + (m - 256)] = v4;
        }
    }
}

// ---------------------------------------------------------------------------
// Kernel 2: CORR[b,p,d] = sum_c QK[b,p,c]*QK[b,p+d,c] for 85 symmetric offsets.
// Tile 4 rows x 8 cols of positions; halo 10x20; channel chunks of 32, float4.
__global__ void kCorr() {
    __shared__ float4 sQ4[10*20*9];          // 10 rows x 20 cols x 36 floats (pad)
    int b  = blockIdx.z;
    int r0 = blockIdx.y * 4;
    int c0 = blockIdx.x * 8;
    int tid = threadIdx.x;
    int pl = tid & 31;                        // position within tile
    int wg = tid >> 5;                        // d-group (warp)
    int pr = pl >> 3, pc = pl & 7;
    int dbase = wg * 11;

    int doff[11];
    #pragma unroll
    for (int k = 0; k < 11; k++) {
        int t = dbase + k; if (t > 84) t = 84;
        int dr, dc;
        if (t < 7) { dr = 0; dc = t; }
        else { int u = t - 7; dr = u/13 + 1; dc = u%13 - 6; }
        doff[k] = (dr*20 + dc) * 9;           // float4 units
    }
    float acc[11];
    #pragma unroll
    for (int k = 0; k < 11; k++) acc[k] = 0.f;

    int own4 = (pr*20 + (pc + 6)) * 9;

    for (int cc = 0; cc < 256; cc += 32) {
        for (int flat = tid; flat < 1600; flat += 256) {   // 200 pos x 8 float4
            int pos = flat >> 3, c4 = flat & 7;
            int hr = pos / 20, hc = pos % 20;
            int gr = r0 + hr, gc = c0 - 6 + hc;
            float4 v = make_float4(0.f, 0.f, 0.f, 0.f);
            if (gr < 54 && gc >= 0 && gc < 54)
                v = *(const float4*)&g_QK[(long)((b*NPOS + gr*54 + gc))*256 + cc + c4*4];
            sQ4[pos*9 + c4] = v;
        }
        __syncthreads();
        #pragma unroll
        for (int c4 = 0; c4 < 8; c4++) {
            float4 q = sQ4[own4 + c4];
            #pragma unroll
            for (int k = 0; k < 11; k++) {
                float4 v = sQ4[own4 + doff[k] + c4];
                acc[k] += q.x*v.x + q.y*v.y + q.z*v.z + q.w*v.w;
            }
        }
        __syncthreads();
    }
    int gr = r0 + pr, gc = c0 + pc;
    if (gr < 54 && gc < 54) {
        float* o = &g_CORR[(long)(b*NPOS + gr*54 + gc)*ND2];
        #pragma unroll
        for (int k = 0; k < 11; k++) {
            int t = dbase + k;
            if (t < 85) o[t] = acc[k];
        }
    }
}

// ---------------------------------------------------------------------------
// Kernel 3: bias projections. AB[p][r] = sum_{o<128} rel_h[o,r]*QK[p][o],
//           AB[p][8+r] = sum_{o<128} rel_w[o,r]*QK[p][128+o]
__global__ void kAB(const float* __restrict__ relh, const float* __restrict__ relw) {
    __shared__ float sRh[7*132];
    __shared__ float sRw[7*132];
    int tid = threadIdx.x;
    for (int i = tid; i < 896; i += 256) {
        int o = i / 7, r = i % 7;
        sRh[r*132 + o] = relh[i];
        sRw[r*132 + o] = relw[i];
    }
    __syncthreads();
    int grp = tid >> 4;            // 16 positions per block
    int e   = tid & 15;
    int p = blockIdx.x * 16 + grp;
    if (p < BB*NPOS) {
        const float* qrow = &g_QK[(long)p*256];
        float acc = 0.f;
        if (e < 7) {
            #pragma unroll 4
            for (int o = 0; o < 128; o++) acc += sRh[e*132 + o] * qrow[o];
        } else if (e >= 8 && e < 15) {
            int r = e - 8;
            #pragma unroll 4
            for (int o = 0; o < 128; o++) acc += sRw[r*132 + o] * qrow[128 + o];
        }
        g_AB[(long)p*16 + e] = acc;
    }
}

// ---------------------------------------------------------------------------
// Kernel 4: per-pixel scores (from CORR + bias), softmax, row-average, V gather.
__global__ void kAttn(float* __restrict__ out) {
    __shared__ float sS[49*49];
    __shared__ float sAB[49*16];
    __shared__ float sW[49];
    __shared__ int   sPJ[49];
    int pix = blockIdx.x;
    int b = pix / 2304, rem = pix % 2304;
    int h = rem / 48, w0 = rem % 48;
    int tid = threadIdx.x;

    if (tid < 49) {
        int jr = tid / 7, jc = tid % 7;
        sPJ[tid] = b*NPOS + (h + jr)*54 + (w0 + jc);
    }
    for (int f = tid; f < 784; f += 128) {
        int jj = f >> 4, e = f & 15;
        int jr = jj / 7, jc = jj % 7;
        sAB[f] = g_AB[(long)(b*NPOS + (h + jr)*54 + (w0 + jc))*16 + e];
    }
    __syncthreads();

    for (int e2 = tid; e2 < 2401; e2 += 128) {
        int ii = e2 / 49, jj = e2 % 49;
        int ir = ii / 7, ic = ii % 7, jr = jj / 7, jc = jj % 7;
        int dr = jr - ir, dc = jc - ic;
        int base;
        if (dr > 0 || (dr == 0 && dc >= 0)) {
            base = (h + ir)*54 + (w0 + ic);
        } else {
            base = (h + jr)*54 + (w0 + jc);
            dr = -dr; dc = -dc;
        }
        int di = (dr == 0) ? dc : (7 + (dr - 1)*13 + dc + 6);
        sS[e2] = g_CORR[(long)(b*NPOS + base)*ND2 + di] + sAB[jj*16 + ir] + sAB[jj*16 + 8 + ic];
    }
    __syncthreads();

    int lane = tid & 31, wid = tid >> 5;
    for (int ii = wid; ii < 49; ii += 4) {
        float v1 = sS[ii*49 + lane];
        bool ok2 = (lane + 32) < 49;
        float v2 = ok2 ? sS[ii*49 + lane + 32] : -1e30f;
        float m = fmaxf(v1, v2);
        #pragma unroll
        for (int o = 16; o; o >>= 1) m = fmaxf(m, __shfl_xor_sync(0xffffffffu, m, o));
        float e1 = __expf(v1 - m);
        float e2v = ok2 ? __expf(v2 - m) : 0.f;
        float s = e1 + e2v;
        #pragma unroll
        for (int o = 16; o; o >>= 1) s += __shfl_xor_sync(0xffffffffu, s, o);
        float inv = 1.f / s;
        sS[ii*49 + lane] = e1 * inv;
        if (ok2) sS[ii*49 + lane + 32] = e2v * inv;
    }
    __syncthreads();

    if (tid < 49) {
        float s = 0.f;
        #pragma unroll 7
        for (int ii = 0; ii < 49; ii++) s += sS[ii*49 + tid];
        sW[tid] = s * (1.f/49.f);
    }
    __syncthreads();

    for (int c = tid; c < 256; c += 128) {
        float acc = 0.f;
        #pragma unroll 7
        for (int jj = 0; jj < 49; jj++)
            acc += sW[jj] * g_V[(long)sPJ[jj]*256 + c];
        out[((b*256 + c)*48 + h)*48 + w0] = acc;
    }
}

// ---------------------------------------------------------------------------
extern "C" void kernel_launch(void* const* d_in, const int* in_sizes, int n_in,
                              void* d_out, int out_size) {
    const float* x    = (const float*)d_in[0];
    const float* wk   = (const float*)d_in[1];
    const float* wv   = (const float*)d_in[2];
    const float* relh = (const float*)d_in[3];
    const float* relw = (const float*)d_in[4];
    float* out = (float*)d_out;

    kZero<<<512, 256>>>();
    kGemm<<<dim3(36, 4), 256>>>(x, wk, wv);
    kCorr<<<dim3(7, 14, 2), 256>>>();
    kAB<<<(BB*NPOS + 15)/16, 256>>>(relh, relw);
    kAttn<<<BB*HH*WW, 128>>>(out);
}

// round 2
// speedup vs baseline: 1.0687x; 1.0687x over previous
#include <cuda_runtime.h>

#define BB 2
#define CIN 256
#define OCH 256
#define HH 48
#define WW 48
#define HP 54
#define WP 54
#define NPOS (HP*WP)      // 2916
#define KS 7
#define KK 49
#define ND2 85            // symmetric offsets: dr=0,dc>=0 (7) + dr in [1,6] x dc in [-6,6] (78)

// Scratch (device globals: no allocation allowed)
__device__ float g_QK[BB*NPOS*OCH];      // [b][p][o]   ~6.0 MB
__device__ float g_V [BB*NPOS*OCH];      // [b][p][o]   ~6.0 MB
__device__ float g_CORR[BB*NPOS*ND2];    // [b][p][d]   ~2.0 MB
__device__ float g_AB[BB*NPOS*16];       // [b][p][0..6]=A(rel_h), [8..14]=B(rel_w)

// packed f32x2 FMA (Blackwell)
__device__ __forceinline__ void ffma2(unsigned long long &d, unsigned long long a, unsigned long long b) {
    asm("fma.rn.f32x2 %0, %1, %2, %0;" : "+l"(d) : "l"(a), "l"(b));
}
__device__ __forceinline__ float2 u2f(unsigned long long u) {
    float2 f; asm("mov.b64 {%0,%1}, %2;" : "=f"(f.x), "=f"(f.y) : "l"(u)); return f;
}

// ---------------------------------------------------------------------------
// Kernel 0: zero only BORDER positions of QK and V (interior overwritten by GEMM).
// Border positions per batch: 612.  Total float4 slots: 2 arrays * 2 b * 612 * 64.
__global__ void kZero() {
    int idx = blockIdx.x * 256 + threadIdx.x;   // grid 612 x 256 = exact count
    int c4  = idx & 63;
    int t   = idx >> 6;
    int bp  = t % 612;
    int t2  = t / 612;
    int b   = t2 & 1;
    int arr = t2 >> 1;
    int row, col;
    if (bp < 324) { int r = bp / 54; row = (r < 3) ? r : r + 48; col = bp % 54; }
    else { int u = bp - 324; row = 3 + u / 6; int c6 = u % 6; col = (c6 < 3) ? c6 : c6 + 48; }
    long off = ((long)(b*NPOS + row*54 + col)*256) + c4*4;
    float4 z = make_float4(0.f, 0.f, 0.f, 0.f);
    if (arr == 0) *(float4*)&g_QK[off] = z;
    else          *(float4*)&g_V [off] = z;
}

// ---------------------------------------------------------------------------
// Kernel 1: fused 1x1 conv GEMM with packed f32x2 FMA.
// C[n, m] = sum_c x[b,c,s(n)] * W[m, c]; n=4608 positions, m=512 (key|value)
// A stored DUPLICATED in smem so a 16B LDS yields two broadcast-pairs.
__global__ void __launch_bounds__(256) kGemm(const float* __restrict__ x,
                                             const float* __restrict__ wk,
                                             const float* __restrict__ wv) {
    __shared__ float As2[16][264];   // duplicated: As2[k][2n] = As2[k][2n+1] = a
    __shared__ float Bs[16][132];
    int tid = threadIdx.x;
    int n0 = blockIdx.x * 128;
    int m0 = blockIdx.y * 128;
    int tx = tid & 15, ty = tid >> 4;
    unsigned long long acc[8][4];
    #pragma unroll
    for (int i = 0; i < 8; i++)
        #pragma unroll
        for (int j = 0; j < 4; j++) acc[i][j] = 0ull;

    for (int kt = 0; kt < 256; kt += 16) {
        #pragma unroll
        for (int i = 0; i < 8; i++) {           // A: 16k x 128n of x, duplicated
            int flat = i*256 + tid;
            int k = flat >> 7, n = flat & 127;
            int nn = n0 + n;
            int b = nn / 2304, s = nn % 2304;   // tiles never straddle b
            float v = x[(b*256 + kt + k)*2304 + s];
            *(float2*)&As2[k][2*n] = make_float2(v, v);
        }
        #pragma unroll
        for (int i = 0; i < 8; i++) {           // B: 16k x 128m of weights
            int flat = i*256 + tid;
            int k = flat & 15, m = flat >> 4;
            int mm = m0 + m;
            Bs[k][m] = (mm < 256) ? wk[mm*256 + kt + k] : wv[(mm-256)*256 + kt + k];
        }
        __syncthreads();
        #pragma unroll
        for (int k = 0; k < 16; k++) {
            ulonglong2 a01 = *(const ulonglong2*)&As2[k][8*ty];        // {a0,a0},{a1,a1}
            ulonglong2 a23 = *(const ulonglong2*)&As2[k][8*ty + 4];
            ulonglong2 a45 = *(const ulonglong2*)&As2[k][128 + 8*ty];
            ulonglong2 a67 = *(const ulonglong2*)&As2[k][128 + 8*ty + 4];
            ulonglong2 b03 = *(const ulonglong2*)&Bs[k][4*tx];         // {b0,b1},{b2,b3}
            ulonglong2 b47 = *(const ulonglong2*)&Bs[k][64 + 4*tx];
            unsigned long long A[8] = {a01.x, a01.y, a23.x, a23.y, a45.x, a45.y, a67.x, a67.y};
            unsigned long long B[4] = {b03.x, b03.y, b47.x, b47.y};
            #pragma unroll
            for (int i = 0; i < 8; i++)
                #pragma unroll
                for (int j = 0; j < 4; j++)
                    ffma2(acc[i][j], A[i], B[j]);
        }
        __syncthreads();
    }
    // epilogue
    #pragma unroll
    for (int i = 0; i < 8; i++) {
        int n = n0 + ((i < 4) ? (ty*4 + i) : (64 + ty*4 + i - 4));
        int b = n / 2304, rem = n % 2304;
        int h = rem / 48, w = rem % 48;
        int pidx = (h + 3)*54 + (w + 3);
        long rowq = (long)(b*NPOS + pidx)*256;
        float2 p0 = u2f(acc[i][0]), p1 = u2f(acc[i][1]);
        float2 p2 = u2f(acc[i][2]), p3 = u2f(acc[i][3]);
        float4 va = make_float4(p0.x, p0.y, p1.x, p1.y);
        float4 vb = make_float4(p2.x, p2.y, p3.x, p3.y);
        int ma = m0 + tx*4;
        int mb = m0 + 64 + tx*4;
        if (ma < 256) *(float4*)&g_QK[rowq + ma]        = va;
        else          *(float4*)&g_V [rowq + (ma-256)]  = va;
        if (mb < 256) *(float4*)&g_QK[rowq + mb]        = vb;
        else          *(float4*)&g_V [rowq + (mb-256)]  = vb;
    }
}

// ---------------------------------------------------------------------------
// Kernel 2: CORR[b,p,d] = sum_c QK[b,p,c]*QK[b,p+d,c] for 85 symmetric offsets.
__global__ void kCorr() {
    __shared__ float4 sQ4[10*20*9];
    int b  = blockIdx.z;
    int r0 = blockIdx.y * 4;
    int c0 = blockIdx.x * 8;
    int tid = threadIdx.x;
    int pl = tid & 31;
    int wg = tid >> 5;
    int pr = pl >> 3, pc = pl & 7;
    int dbase = wg * 11;

    int doff[11];
    #pragma unroll
    for (int k = 0; k < 11; k++) {
        int t = dbase + k; if (t > 84) t = 84;
        int dr, dc;
        if (t < 7) { dr = 0; dc = t; }
        else { int u = t - 7; dr = u/13 + 1; dc = u%13 - 6; }
        doff[k] = (dr*20 + dc) * 9;
    }
    float acc[11];
    #pragma unroll
    for (int k = 0; k < 11; k++) acc[k] = 0.f;

    int own4 = (pr*20 + (pc + 6)) * 9;

    for (int cc = 0; cc < 256; cc += 32) {
        for (int flat = tid; flat < 1600; flat += 256) {
            int pos = flat >> 3, c4 = flat & 7;
            int hr = pos / 20, hc = pos % 20;
            int gr = r0 + hr, gc = c0 - 6 + hc;
            float4 v = make_float4(0.f, 0.f, 0.f, 0.f);
            if (gr < 54 && gc >= 0 && gc < 54)
                v = *(const float4*)&g_QK[(long)((b*NPOS + gr*54 + gc))*256 + cc + c4*4];
            sQ4[pos*9 + c4] = v;
        }
        __syncthreads();
        #pragma unroll
        for (int c4 = 0; c4 < 8; c4++) {
            float4 q = sQ4[own4 + c4];
            #pragma unroll
            for (int k = 0; k < 11; k++) {
                float4 v = sQ4[own4 + doff[k] + c4];
                acc[k] += q.x*v.x + q.y*v.y + q.z*v.z + q.w*v.w;
            }
        }
        __syncthreads();
    }
    int gr = r0 + pr, gc = c0 + pc;
    if (gr < 54 && gc < 54) {
        float* o = &g_CORR[(long)(b*NPOS + gr*54 + gc)*ND2];
        #pragma unroll
        for (int k = 0; k < 11; k++) {
            int t = dbase + k;
            if (t < 85) o[t] = acc[k];
        }
    }
}

// ---------------------------------------------------------------------------
// Kernel 3: bias projections, warp-per-position, float4 coalesced.
// AB[p][r] = sum_{o<128} rel_h[o,r]*QK[p][o];  AB[p][8+r] = sum rel_w[o,r]*QK[p][128+o]
__global__ void __launch_bounds__(256) kAB(const float* __restrict__ relh,
                                           const float* __restrict__ relw) {
    __shared__ float sR[2][7][128];   // [half][r][o]
    int tid = threadIdx.x;
    for (int i = tid; i < 1792; i += 256) {
        int half = i / 896, j = i % 896;
        int r = j / 128, o = j % 128;
        sR[half][r][o] = (half == 0) ? relh[o*7 + r] : relw[o*7 + r];
    }
    __syncthreads();

    int lane = tid & 31, wid = tid >> 5;
    int p = blockIdx.x * 8 + wid;           // grid = 729 -> 5832 exact
    const float* qrow = &g_QK[(long)p*256];
    float4 q1 = *(const float4*)&qrow[4*lane];
    float4 q2 = *(const float4*)&qrow[128 + 4*lane];

    #pragma unroll
    for (int r = 0; r < 7; r++) {
        float4 rh = *(const float4*)&sR[0][r][4*lane];
        float4 rw = *(const float4*)&sR[1][r][4*lane];
        float sh = rh.x*q1.x + rh.y*q1.y + rh.z*q1.z + rh.w*q1.w;
        float sw = rw.x*q2.x + rw.y*q2.y + rw.z*q2.z + rw.w*q2.w;
        #pragma unroll
        for (int o = 16; o; o >>= 1) {
            sh += __shfl_xor_sync(0xffffffffu, sh, o);
            sw += __shfl_xor_sync(0xffffffffu, sw, o);
        }
        if (lane == 0) {
            g_AB[(long)p*16 + r]     = sh;
            g_AB[(long)p*16 + 8 + r] = sw;
        }
    }
}

// ---------------------------------------------------------------------------
// Kernel 4: per-pixel scores, softmax, row-average, float2-vectorized V gather.
__global__ void __launch_bounds__(128) kAttn(float* __restrict__ out) {
    __shared__ float sS[49*49];
    __shared__ float sAB[49*16];
    __shared__ float sW[49];
    __shared__ int   sPJ[49];
    int pix = blockIdx.x;
    int b = pix / 2304, rem = pix % 2304;
    int h = rem / 48, w0 = rem % 48;
    int tid = threadIdx.x;

    if (tid < 49) {
        int jr = tid / 7, jc = tid % 7;
        sPJ[tid] = b*NPOS + (h + jr)*54 + (w0 + jc);
    }
    for (int f = tid; f < 784; f += 128) {
        int jj = f >> 4, e = f & 15;
        int jr = jj / 7, jc = jj % 7;
        sAB[f] = g_AB[(long)(b*NPOS + (h + jr)*54 + (w0 + jc))*16 + e];
    }
    __syncthreads();

    for (int e2 = tid; e2 < 2401; e2 += 128) {
        int ii = e2 / 49, jj = e2 % 49;
        int ir = ii / 7, ic = ii % 7, jr = jj / 7, jc = jj % 7;
        int dr = jr - ir, dc = jc - ic;
        int base;
        if (dr > 0 || (dr == 0 && dc >= 0)) {
            base = (h + ir)*54 + (w0 + ic);
        } else {
            base = (h + jr)*54 + (w0 + jc);
            dr = -dr; dc = -dc;
        }
        int di = (dr == 0) ? dc : (7 + (dr - 1)*13 + dc + 6);
        sS[e2] = g_CORR[(long)(b*NPOS + base)*ND2 + di] + sAB[jj*16 + ir] + sAB[jj*16 + 8 + ic];
    }
    __syncthreads();

    int lane = tid & 31, wid = tid >> 5;
    for (int ii = wid; ii < 49; ii += 4) {
        float v1 = sS[ii*49 + lane];
        bool ok2 = (lane + 32) < 49;
        float v2 = ok2 ? sS[ii*49 + lane + 32] : -1e30f;
        float m = fmaxf(v1, v2);
        #pragma unroll
        for (int o = 16; o; o >>= 1) m = fmaxf(m, __shfl_xor_sync(0xffffffffu, m, o));
        float e1 = __expf(v1 - m);
        float e2v = ok2 ? __expf(v2 - m) : 0.f;
        float s = e1 + e2v;
        #pragma unroll
        for (int o = 16; o; o >>= 1) s += __shfl_xor_sync(0xffffffffu, s, o);
        float inv = 1.f / s;
        sS[ii*49 + lane] = e1 * inv;
        if (ok2) sS[ii*49 + lane + 32] = e2v * inv;
    }
    __syncthreads();

    if (tid < 49) {
        float s = 0.f;
        #pragma unroll 7
        for (int ii = 0; ii < 49; ii++) s += sS[ii*49 + tid];
        sW[tid] = s * (1.f/49.f);
    }
    __syncthreads();

    // V gather: thread handles channels {2*tid, 2*tid+1} via float2
    {
        float2 acc = make_float2(0.f, 0.f);
        #pragma unroll 7
        for (int jj = 0; jj < 49; jj++) {
            float w = sW[jj];
            float2 v = *(const float2*)&g_V[(long)sPJ[jj]*256 + 2*tid];
            acc.x += w * v.x;
            acc.y += w * v.y;
        }
        int c = 2*tid;
        out[((b*256 + c    )*48 + h)*48 + w0] = acc.x;
        out[((b*256 + c + 1)*48 + h)*48 + w0] = acc.y;
    }
}

// ---------------------------------------------------------------------------
extern "C" void kernel_launch(void* const* d_in, const int* in_sizes, int n_in,
                              void* d_out, int out_size) {
    const float* x    = (const float*)d_in[0];
    const float* wk   = (const float*)d_in[1];
    const float* wv   = (const float*)d_in[2];
    const float* relh = (const float*)d_in[3];
    const float* relw = (const float*)d_in[4];
    float* out = (float*)d_out;

    kZero<<<612, 256>>>();
    kGemm<<<dim3(36, 4), 256>>>(x, wk, wv);
    kCorr<<<dim3(7, 14, 2), 256>>>();
    kAB<<<729, 256>>>(relh, relw);
    kAttn<<<BB*HH*WW, 128>>>(out);
}

// round 3
// speedup vs baseline: 1.2073x; 1.1297x over previous
#include <cuda_runtime.h>

#define BB 2
#define CIN 256
#define OCH 256
#define HH 48
#define WW 48
#define HP 54
#define WP 54
#define NPOS (HP*WP)      // 2916
#define NP2 (BB*NPOS)     // 5832
#define KS 7
#define KK 49
#define ND2 85            // symmetric offsets: dr=0,dc>=0 (7) + dr in [1,6] x dc in [-6,6] (78)

// Scratch (device globals: no allocation allowed)
__device__ float g_QK[BB*NPOS*OCH];      // [b][p][o]   ~6.0 MB
__device__ float g_V [BB*NPOS*OCH];      // [b][p][o]   ~6.0 MB
__device__ float g_CORR[ND2*NP2];        // [d][b*NPOS+p]  ~2.0 MB  (offset-major!)
__device__ float g_AB[BB*NPOS*16];       // [b][p][0..6]=A(rel_h), [8..14]=B(rel_w)

// packed f32x2 FMA (Blackwell)
__device__ __forceinline__ void ffma2(unsigned long long &d, unsigned long long a, unsigned long long b) {
    asm("fma.rn.f32x2 %0, %1, %2, %0;" : "+l"(d) : "l"(a), "l"(b));
}
__device__ __forceinline__ float2 u2f(unsigned long long u) {
    float2 f; asm("mov.b64 {%0,%1}, %2;" : "=f"(f.x), "=f"(f.y) : "l"(u)); return f;
}

// ---------------------------------------------------------------------------
// Kernel 0: zero only BORDER positions of QK and V (interior overwritten by GEMM).
__global__ void kZero() {
    int idx = blockIdx.x * 256 + threadIdx.x;   // grid 612 x 256 = exact count
    int c4  = idx & 63;
    int t   = idx >> 6;
    int bp  = t % 612;
    int t2  = t / 612;
    int b   = t2 & 1;
    int arr = t2 >> 1;
    int row, col;
    if (bp < 324) { int r = bp / 54; row = (r < 3) ? r : r + 48; col = bp % 54; }
    else { int u = bp - 324; row = 3 + u / 6; int c6 = u % 6; col = (c6 < 3) ? c6 : c6 + 48; }
    long off = ((long)(b*NPOS + row*54 + col)*256) + c4*4;
    float4 z = make_float4(0.f, 0.f, 0.f, 0.f);
    if (arr == 0) *(float4*)&g_QK[off] = z;
    else          *(float4*)&g_V [off] = z;
}

// ---------------------------------------------------------------------------
// Kernel 1: fused 1x1 conv GEMM with packed f32x2 FMA.
__global__ void __launch_bounds__(256) kGemm(const float* __restrict__ x,
                                             const float* __restrict__ wk,
                                             const float* __restrict__ wv) {
    __shared__ float As2[16][264];   // duplicated: As2[k][2n] = As2[k][2n+1] = a
    __shared__ float Bs[16][132];
    int tid = threadIdx.x;
    int n0 = blockIdx.x * 128;
    int m0 = blockIdx.y * 128;
    int tx = tid & 15, ty = tid >> 4;
    unsigned long long acc[8][4];
    #pragma unroll
    for (int i = 0; i < 8; i++)
        #pragma unroll
        for (int j = 0; j < 4; j++) acc[i][j] = 0ull;

    for (int kt = 0; kt < 256; kt += 16) {
        #pragma unroll
        for (int i = 0; i < 8; i++) {
            int flat = i*256 + tid;
            int k = flat >> 7, n = flat & 127;
            int nn = n0 + n;
            int b = nn / 2304, s = nn % 2304;
            float v = x[(b*256 + kt + k)*2304 + s];
            *(float2*)&As2[k][2*n] = make_float2(v, v);
        }
        #pragma unroll
        for (int i = 0; i < 8; i++) {
            int flat = i*256 + tid;
            int k = flat & 15, m = flat >> 4;
            int mm = m0 + m;
            Bs[k][m] = (mm < 256) ? wk[mm*256 + kt + k] : wv[(mm-256)*256 + kt + k];
        }
        __syncthreads();
        #pragma unroll
        for (int k = 0; k < 16; k++) {
            ulonglong2 a01 = *(const ulonglong2*)&As2[k][8*ty];
            ulonglong2 a23 = *(const ulonglong2*)&As2[k][8*ty + 4];
            ulonglong2 a45 = *(const ulonglong2*)&As2[k][128 + 8*ty];
            ulonglong2 a67 = *(const ulonglong2*)&As2[k][128 + 8*ty + 4];
            ulonglong2 b03 = *(const ulonglong2*)&Bs[k][4*tx];
            ulonglong2 b47 = *(const ulonglong2*)&Bs[k][64 + 4*tx];
            unsigned long long A[8] = {a01.x, a01.y, a23.x, a23.y, a45.x, a45.y, a67.x, a67.y};
            unsigned long long B[4] = {b03.x, b03.y, b47.x, b47.y};
            #pragma unroll
            for (int i = 0; i < 8; i++)
                #pragma unroll
                for (int j = 0; j < 4; j++)
                    ffma2(acc[i][j], A[i], B[j]);
        }
        __syncthreads();
    }
    #pragma unroll
    for (int i = 0; i < 8; i++) {
        int n = n0 + ((i < 4) ? (ty*4 + i) : (64 + ty*4 + i - 4));
        int b = n / 2304, rem = n % 2304;
        int h = rem / 48, w = rem % 48;
        int pidx = (h + 3)*54 + (w + 3);
        long rowq = (long)(b*NPOS + pidx)*256;
        float2 p0 = u2f(acc[i][0]), p1 = u2f(acc[i][1]);
        float2 p2 = u2f(acc[i][2]), p3 = u2f(acc[i][3]);
        float4 va = make_float4(p0.x, p0.y, p1.x, p1.y);
        float4 vb = make_float4(p2.x, p2.y, p3.x, p3.y);
        int ma = m0 + tx*4;
        int mb = m0 + 64 + tx*4;
        if (ma < 256) *(float4*)&g_QK[rowq + ma]        = va;
        else          *(float4*)&g_V [rowq + (ma-256)]  = va;
        if (mb < 256) *(float4*)&g_QK[rowq + mb]        = vb;
        else          *(float4*)&g_V [rowq + (mb-256)]  = vb;
    }
}

// ---------------------------------------------------------------------------
// Kernel 2: CORR[d][b,p] = sum_c QK[b,p,c]*QK[b,p+d,c] for 85 symmetric offsets.
__global__ void kCorr() {
    __shared__ float4 sQ4[10*20*9];
    int b  = blockIdx.z;
    int r0 = blockIdx.y * 4;
    int c0 = blockIdx.x * 8;
    int tid = threadIdx.x;
    int pl = tid & 31;
    int wg = tid >> 5;
    int pr = pl >> 3, pc = pl & 7;
    int dbase = wg * 11;

    int doff[11];
    #pragma unroll
    for (int k = 0; k < 11; k++) {
        int t = dbase + k; if (t > 84) t = 84;
        int dr, dc;
        if (t < 7) { dr = 0; dc = t; }
        else { int u = t - 7; dr = u/13 + 1; dc = u%13 - 6; }
        doff[k] = (dr*20 + dc) * 9;
    }
    float acc[11];
    #pragma unroll
    for (int k = 0; k < 11; k++) acc[k] = 0.f;

    int own4 = (pr*20 + (pc + 6)) * 9;

    for (int cc = 0; cc < 256; cc += 32) {
        for (int flat = tid; flat < 1600; flat += 256) {
            int pos = flat >> 3, c4 = flat & 7;
            int hr = pos / 20, hc = pos % 20;
            int gr = r0 + hr, gc = c0 - 6 + hc;
            float4 v = make_float4(0.f, 0.f, 0.f, 0.f);
            if (gr < 54 && gc >= 0 && gc < 54)
                v = *(const float4*)&g_QK[(long)((b*NPOS + gr*54 + gc))*256 + cc + c4*4];
            sQ4[pos*9 + c4] = v;
        }
        __syncthreads();
        #pragma unroll
        for (int c4 = 0; c4 < 8; c4++) {
            float4 q = sQ4[own4 + c4];
            #pragma unroll
            for (int k = 0; k < 11; k++) {
                float4 v = sQ4[own4 + doff[k] + c4];
                acc[k] += q.x*v.x + q.y*v.y + q.z*v.z + q.w*v.w;
            }
        }
        __syncthreads();
    }
    int gr = r0 + pr, gc = c0 + pc;
    if (gr < 54 && gc < 54) {
        int pg = b*NPOS + gr*54 + gc;
        #pragma unroll
        for (int k = 0; k < 11; k++) {
            int t = dbase + k;
            if (t < 85) g_CORR[t*NP2 + pg] = acc[k];
        }
    }
}

// ---------------------------------------------------------------------------
// Kernel 3: bias projections, warp-per-position, float4 coalesced.
__global__ void __launch_bounds__(256) kAB(const float* __restrict__ relh,
                                           const float* __restrict__ relw) {
    __shared__ float sR[2][7][128];
    int tid = threadIdx.x;
    for (int i = tid; i < 1792; i += 256) {
        int half = i / 896, j = i % 896;
        int r = j / 128, o = j % 128;
        sR[half][r][o] = (half == 0) ? relh[o*7 + r] : relw[o*7 + r];
    }
    __syncthreads();

    int lane = tid & 31, wid = tid >> 5;
    int p = blockIdx.x * 8 + wid;
    const float* qrow = &g_QK[(long)p*256];
    float4 q1 = *(const float4*)&qrow[4*lane];
    float4 q2 = *(const float4*)&qrow[128 + 4*lane];

    #pragma unroll
    for (int r = 0; r < 7; r++) {
        float4 rh = *(const float4*)&sR[0][r][4*lane];
        float4 rw = *(const float4*)&sR[1][r][4*lane];
        float sh = rh.x*q1.x + rh.y*q1.y + rh.z*q1.z + rh.w*q1.w;
        float sw = rw.x*q2.x + rw.y*q2.y + rw.z*q2.z + rw.w*q2.w;
        #pragma unroll
        for (int o = 16; o; o >>= 1) {
            sh += __shfl_xor_sync(0xffffffffu, sh, o);
            sw += __shfl_xor_sync(0xffffffffu, sw, o);
        }
        if (lane == 0) {
            g_AB[(long)p*16 + r]     = sh;
            g_AB[(long)p*16 + 8 + r] = sw;
        }
    }
}

// ---------------------------------------------------------------------------
// Kernel 4: 16-pixel row-strip per block. Coalesced CORR gather (offset-major),
// chunked smem-staged scores + width-16 shfl softmax, smem-staged V gather.
// smem union (bytes):
//   [0     .. 41888)  sV   154 pos x 68 floats         (phase C)
//   [0     ..  9604)  sTab 2401 ints                   (phase B; dead in C)
//   [9616  .. 19920)  sABt 16 x 161 floats             (phase B; dead in C)
//   [19920 .. 43244)  sS   7 x 49 x 17 floats          (phase B; dead in C)
//   [41888 .. 45220)  sWv  49 x 17 floats  (written after final B sync; overlaps sS tail safely)
__global__ void __launch_bounds__(256) kAttn(float* __restrict__ out) {
    __shared__ __align__(16) char smem[45248];
    int*   sTab = (int*)smem;
    float* sABt = (float*)(smem + 9616);
    float* sS   = (float*)(smem + 19920);
    float* sV   = (float*)smem;
    float* sWv  = (float*)(smem + 41888);

    int tid = threadIdx.x;
    int w0 = blockIdx.x * 16;
    int h  = blockIdx.y;
    int b  = blockIdx.z;
    int bbase = b*NPOS;

    // Build (ii,jj) -> packed index table
    for (int e = tid; e < 2401; e += 256) {
        int ii = e / 49, jj = e % 49;
        int ir = ii / 7, ic = ii % 7, jr = jj / 7, jc = jj % 7;
        int dr = jr - ir, dc = jc - ic, r, c;
        if (dr > 0 || (dr == 0 && dc >= 0)) { r = ir; c = ic; }
        else { r = jr; c = jc; dr = -dr; dc = -dc; }
        int di = (dr == 0) ? dc : (7 + (dr-1)*13 + dc + 6);
        sTab[e] = di | (r<<7) | (c<<10) | (ir<<13) | (ic<<16) | (jr<<19) | (jc<<22);
    }
    // Stage bias projections for the 7x22 position region, transposed [e][pos]
    for (int i = tid; i < 2464; i += 256) {
        int e = i & 15, p2 = i >> 4;
        int r = p2 / 22, cpos = p2 % 22;
        sABt[e*161 + p2] = g_AB[(long)(bbase + (h+r)*54 + w0 + cpos)*16 + e];
    }
    __syncthreads();

    float wacc0 = 0.f, wacc1 = 0.f, wacc2 = 0.f, wacc3 = 0.f;
    int px_b = tid >> 4, tg = tid & 15;   // B2 mapping: lanes 0-15 = one px

    for (int chk = 0; chk < 7; chk++) {
        int ii0 = chk*7;
        // B1: scores for 7 rows x 49 x 16 px, pixel-coalesced CORR loads
        for (int f = tid; f < 5488; f += 256) {
            int px = f & 15, q = f >> 4;
            int jj = q % 49, rr = q / 49;
            int t = sTab[(ii0+rr)*49 + jj];
            int di = t & 127, r = (t>>7)&7, c = (t>>10)&7;
            int ir = (t>>13)&7, ic = (t>>16)&7, jr = (t>>19)&7, jc = (t>>22)&7;
            int jpos = jr*22 + jc + px;
            float s = g_CORR[di*NP2 + bbase + (h+r)*54 + w0 + c + px]
                    + sABt[ir*161 + jpos]
                    + sABt[(8+ic)*161 + jpos];
            sS[(rr*49 + jj)*17 + px] = s;
        }
        __syncthreads();
        // B2: row softmax (width-16 shfl) + accumulate column sums
        for (int rr = 0; rr < 7; rr++) {
            float v0 = sS[(rr*49 + tg     )*17 + px_b];
            float v1 = sS[(rr*49 + tg + 16)*17 + px_b];
            float v2 = sS[(rr*49 + tg + 32)*17 + px_b];
            float v3 = (tg == 0) ? sS[(rr*49 + 48)*17 + px_b] : -1e30f;
            float m = fmaxf(fmaxf(v0, v1), fmaxf(v2, v3));
            #pragma unroll
            for (int o = 8; o; o >>= 1) m = fmaxf(m, __shfl_xor_sync(0xffffffffu, m, o, 16));
            float e0 = __expf(v0 - m), e1 = __expf(v1 - m), e2 = __expf(v2 - m);
            float e3 = (tg == 0) ? __expf(v3 - m) : 0.f;
            float s = e0 + e1 + e2 + e3;
            #pragma unroll
            for (int o = 8; o; o >>= 1) s += __shfl_xor_sync(0xffffffffu, s, o, 16);
            float inv = 1.f / s;
            wacc0 += e0*inv; wacc1 += e1*inv; wacc2 += e2*inv; wacc3 += e3*inv;
        }
        __syncthreads();   // protects sS for next chunk AND sWv overlap below
    }
    sWv[(tg     )*17 + px_b] = wacc0 * (1.f/49.f);
    sWv[(tg + 16)*17 + px_b] = wacc1 * (1.f/49.f);
    sWv[(tg + 32)*17 + px_b] = wacc2 * (1.f/49.f);
    if (tg == 0) sWv[48*17 + px_b] = wacc3 * (1.f/49.f);
    __syncthreads();

    // Phase C: V gather via smem staging, 64-channel chunks
    int px = tid & 15, tc = tid >> 4;   // C mapping: px in lanes -> coalesced
    for (int cc = 0; cc < 256; cc += 64) {
        for (int i = tid; i < 2464; i += 256) {
            int f4 = i & 15, p2 = i >> 4;
            int r = p2 / 22, cpos = p2 % 22;
            float4 v = *(const float4*)&g_V[(long)(bbase + (h+r)*54 + w0 + cpos)*256 + cc + f4*4];
            *(float4*)&sV[p2*68 + f4*4] = v;
        }
        __syncthreads();
        float4 acc = make_float4(0.f, 0.f, 0.f, 0.f);
        #pragma unroll
        for (int jj = 0; jj < 49; jj++) {
            int jr = jj/7, jc = jj%7;
            float w = sWv[jj*17 + px];
            float4 v = *(const float4*)&sV[(jr*22 + jc + px)*68 + tc*4];
            acc.x += w*v.x; acc.y += w*v.y; acc.z += w*v.z; acc.w += w*v.w;
        }
        int ob = ((b*256 + cc + tc*4)*48 + h)*48 + w0 + px;
        out[ob]        = acc.x;
        out[ob + 2304] = acc.y;
        out[ob + 4608] = acc.z;
        out[ob + 6912] = acc.w;
        __syncthreads();
    }
}

// ---------------------------------------------------------------------------
extern "C" void kernel_launch(void* const* d_in, const int* in_sizes, int n_in,
                              void* d_out, int out_size) {
    const float* x    = (const float*)d_in[0];
    const float* wk   = (const float*)d_in[1];
    const float* wv   = (const float*)d_in[2];
    const float* relh = (const float*)d_in[3];
    const float* relw = (const float*)d_in[4];
    float* out = (float*)d_out;

    kZero<<<612, 256>>>();
    kGemm<<<dim3(36, 4), 256>>>(x, wk, wv);
    kCorr<<<dim3(7, 14, 2), 256>>>();
    kAB<<<729, 256>>>(relh, relw);
    kAttn<<<dim3(3, 48, 2), 256>>>(out);
}

// round 4
// speedup vs baseline: 1.4792x; 1.2252x over previous
#include <cuda_runtime.h>

#define BB 2
#define CIN 256
#define OCH 256
#define HH 48
#define WW 48
#define HP 54
#define WP 54
#define NPOS (HP*WP)      // 2916
#define NP2 (BB*NPOS)     // 5832
#define KS 7
#define KK 49
#define ND2 85            // symmetric offsets: dr=0,dc>=0 (7) + dr in [1,6] x dc in [-6,6] (78)

// Scratch (device globals: no allocation allowed)
__device__ float g_QK[BB*NPOS*OCH];      // [b][p][o]   ~6.0 MB
__device__ float g_V [BB*NPOS*OCH];      // [b][p][o]   ~6.0 MB
__device__ float g_CORR[ND2*NP2];        // [d][b*NPOS+p]  ~2.0 MB  (offset-major)
__device__ float g_AB[BB*NPOS*16];       // [b][p][0..6]=A(rel_h), [8..14]=B(rel_w)

// packed f32x2 FMA (Blackwell)
__device__ __forceinline__ void ffma2(unsigned long long &d, unsigned long long a, unsigned long long b) {
    asm("fma.rn.f32x2 %0, %1, %2, %0;" : "+l"(d) : "l"(a), "l"(b));
}
__device__ __forceinline__ float2 u2f(unsigned long long u) {
    float2 f; asm("mov.b64 {%0,%1}, %2;" : "=f"(f.x), "=f"(f.y) : "l"(u)); return f;
}
__device__ __forceinline__ unsigned long long dup2(float a) {
    unsigned long long r; asm("mov.b64 %0, {%1, %1};" : "=l"(r) : "f"(a)); return r;
}

// ---------------------------------------------------------------------------
// Kernel 1: fused {border-zero + 1x1 conv GEMM}.
// y<4: GEMM 128x128 tile; y==4: zero border positions of QK/V.
__global__ void __launch_bounds__(256) kGemmZ(const float* __restrict__ x,
                                              const float* __restrict__ wk,
                                              const float* __restrict__ wv) {
    if (blockIdx.y == 4) {       // border zeroing: 2 arrays x 2 b x 612 pos x 64 float4
        float4 z = make_float4(0.f, 0.f, 0.f, 0.f);
        for (int idx = blockIdx.x*256 + threadIdx.x; idx < 156672; idx += 9216) {
            int c4  = idx & 63;
            int t   = idx >> 6;
            int bp  = t % 612;
            int t2  = t / 612;
            int b   = t2 & 1;
            int arr = t2 >> 1;
            int row, col;
            if (bp < 324) { int r = bp / 54; row = (r < 3) ? r : r + 48; col = bp % 54; }
            else { int u = bp - 324; row = 3 + u / 6; int c6 = u % 6; col = (c6 < 3) ? c6 : c6 + 48; }
            long off = ((long)(b*NPOS + row*54 + col)*256) + c4*4;
            if (arr == 0) *(float4*)&g_QK[off] = z;
            else          *(float4*)&g_V [off] = z;
        }
        return;
    }
    __shared__ float As[16][132];
    __shared__ float Bs[16][132];
    int tid = threadIdx.x;
    int n0 = blockIdx.x * 128;
    int m0 = blockIdx.y * 128;
    int tx = tid & 15, ty = tid >> 4;
    unsigned long long acc[8][4];
    #pragma unroll
    for (int i = 0; i < 8; i++)
        #pragma unroll
        for (int j = 0; j < 4; j++) acc[i][j] = 0ull;

    for (int kt = 0; kt < 256; kt += 16) {
        #pragma unroll
        for (int i = 0; i < 8; i++) {
            int flat = i*256 + tid;
            int k = flat >> 7, n = flat & 127;
            int nn = n0 + n;
            int b = nn / 2304, s = nn % 2304;
            As[k][n] = x[(b*256 + kt + k)*2304 + s];
        }
        #pragma unroll
        for (int i = 0; i < 8; i++) {
            int flat = i*256 + tid;
            int k = flat & 15, m = flat >> 4;
            int mm = m0 + m;
            Bs[k][m] = (mm < 256) ? wk[mm*256 + kt + k] : wv[(mm-256)*256 + kt + k];
        }
        __syncthreads();
        #pragma unroll
        for (int k = 0; k < 16; k++) {
            float4 a03 = *(const float4*)&As[k][4*ty];
            float4 a47 = *(const float4*)&As[k][64 + 4*ty];
            ulonglong2 b03 = *(const ulonglong2*)&Bs[k][4*tx];
            ulonglong2 b47 = *(const ulonglong2*)&Bs[k][64 + 4*tx];
            unsigned long long A[8] = {dup2(a03.x), dup2(a03.y), dup2(a03.z), dup2(a03.w),
                                       dup2(a47.x), dup2(a47.y), dup2(a47.z), dup2(a47.w)};
            unsigned long long B[4] = {b03.x, b03.y, b47.x, b47.y};
            #pragma unroll
            for (int i = 0; i < 8; i++)
                #pragma unroll
                for (int j = 0; j < 4; j++)
                    ffma2(acc[i][j], A[i], B[j]);
        }
        __syncthreads();
    }
    #pragma unroll
    for (int i = 0; i < 8; i++) {
        int n = n0 + ((i < 4) ? (ty*4 + i) : (64 + ty*4 + i - 4));
        int b = n / 2304, rem = n % 2304;
        int h = rem / 48, w = rem % 48;
        int pidx = (h + 3)*54 + (w + 3);
        long rowq = (long)(b*NPOS + pidx)*256;
        float2 p0 = u2f(acc[i][0]), p1 = u2f(acc[i][1]);
        float2 p2 = u2f(acc[i][2]), p3 = u2f(acc[i][3]);
        float4 va = make_float4(p0.x, p0.y, p1.x, p1.y);
        float4 vb = make_float4(p2.x, p2.y, p3.x, p3.y);
        int ma = m0 + tx*4;
        int mb = m0 + 64 + tx*4;
        if (ma < 256) *(float4*)&g_QK[rowq + ma]        = va;
        else          *(float4*)&g_V [rowq + (ma-256)]  = va;
        if (mb < 256) *(float4*)&g_QK[rowq + mb]        = vb;
        else          *(float4*)&g_V [rowq + (mb-256)]  = vb;
    }
}

// ---------------------------------------------------------------------------
// Kernel 2: CORR[d][b,p] = sum_c QK[b,p,c]*QK[b,p+d,c] for 85 symmetric offsets.
__global__ void kCorr() {
    __shared__ float4 sQ4[10*20*9];
    int b  = blockIdx.z;
    int r0 = blockIdx.y * 4;
    int c0 = blockIdx.x * 8;
    int tid = threadIdx.x;
    int pl = tid & 31;
    int wg = tid >> 5;
    int pr = pl >> 3, pc = pl & 7;
    int dbase = wg * 11;

    int doff[11];
    #pragma unroll
    for (int k = 0; k < 11; k++) {
        int t = dbase + k; if (t > 84) t = 84;
        int dr, dc;
        if (t < 7) { dr = 0; dc = t; }
        else { int u = t - 7; dr = u/13 + 1; dc = u%13 - 6; }
        doff[k] = (dr*20 + dc) * 9;
    }
    float acc[11];
    #pragma unroll
    for (int k = 0; k < 11; k++) acc[k] = 0.f;

    int own4 = (pr*20 + (pc + 6)) * 9;

    for (int cc = 0; cc < 256; cc += 32) {
        #pragma unroll
        for (int it = 0; it < 7; it++) {
            int flat = it*256 + tid;
            if (flat < 1600) {
                int pos = flat >> 3, c4 = flat & 7;
                int hr = pos / 20, hc = pos % 20;
                int gr = r0 + hr, gc = c0 - 6 + hc;
                float4 v = make_float4(0.f, 0.f, 0.f, 0.f);
                if (gr < 54 && gc >= 0 && gc < 54)
                    v = *(const float4*)&g_QK[(long)((b*NPOS + gr*54 + gc))*256 + cc + c4*4];
                sQ4[pos*9 + c4] = v;
            }
        }
        __syncthreads();
        #pragma unroll
        for (int c4 = 0; c4 < 8; c4++) {
            float4 q = sQ4[own4 + c4];
            #pragma unroll
            for (int k = 0; k < 11; k++) {
                float4 v = sQ4[own4 + doff[k] + c4];
                acc[k] += q.x*v.x + q.y*v.y + q.z*v.z + q.w*v.w;
            }
        }
        __syncthreads();
    }
    int gr = r0 + pr, gc = c0 + pc;
    if (gr < 54 && gc < 54) {
        int pg = b*NPOS + gr*54 + gc;
        #pragma unroll
        for (int k = 0; k < 11; k++) {
            int t = dbase + k;
            if (t < 85) g_CORR[t*NP2 + pg] = acc[k];
        }
    }
}

// ---------------------------------------------------------------------------
// Kernel 3: bias projections, warp-per-position, float4 coalesced.
__global__ void __launch_bounds__(256) kAB(const float* __restrict__ relh,
                                           const float* __restrict__ relw) {
    __shared__ float sR[2][7][128];
    int tid = threadIdx.x;
    for (int i = tid; i < 1792; i += 256) {
        int half = i / 896, j = i % 896;
        int r = j / 128, o = j % 128;
        sR[half][r][o] = (half == 0) ? relh[o*7 + r] : relw[o*7 + r];
    }
    __syncthreads();

    int lane = tid & 31, wid = tid >> 5;
    int p = blockIdx.x * 8 + wid;
    const float* qrow = &g_QK[(long)p*256];
    float4 q1 = *(const float4*)&qrow[4*lane];
    float4 q2 = *(const float4*)&qrow[128 + 4*lane];

    #pragma unroll
    for (int r = 0; r < 7; r++) {
        float4 rh = *(const float4*)&sR[0][r][4*lane];
        float4 rw = *(const float4*)&sR[1][r][4*lane];
        float sh = rh.x*q1.x + rh.y*q1.y + rh.z*q1.z + rh.w*q1.w;
        float sw = rw.x*q2.x + rw.y*q2.y + rw.z*q2.z + rw.w*q2.w;
        #pragma unroll
        for (int o = 16; o; o >>= 1) {
            sh += __shfl_xor_sync(0xffffffffu, sh, o);
            sw += __shfl_xor_sync(0xffffffffu, sw, o);
        }
        if (lane == 0) {
            g_AB[(long)p*16 + r]     = sh;
            g_AB[(long)p*16 + 8 + r] = sw;
        }
    }
}

// ---------------------------------------------------------------------------
// Kernel 4: 16-pixel row-strip per block; unrolled loops for MLP.
__global__ void __launch_bounds__(256) kAttn(float* __restrict__ out) {
    __shared__ __align__(16) char smem[45248];
    int*   sTab = (int*)smem;
    float* sABt = (float*)(smem + 9616);
    float* sS   = (float*)(smem + 19920);
    float* sV   = (float*)smem;
    float* sWv  = (float*)(smem + 41888);

    int tid = threadIdx.x;
    int w0 = blockIdx.x * 16;
    int h  = blockIdx.y;
    int b  = blockIdx.z;
    int bbase = b*NPOS;

    // Build (ii,jj) -> packed index table  (2401 = 9*256 + 97)
    #pragma unroll
    for (int it = 0; it < 10; it++) {
        int e = it*256 + tid;
        if (e < 2401) {
            int ii = e / 49, jj = e % 49;
            int ir = ii / 7, ic = ii % 7, jr = jj / 7, jc = jj % 7;
            int dr = jr - ir, dc = jc - ic, r, c;
            if (dr > 0 || (dr == 0 && dc >= 0)) { r = ir; c = ic; }
            else { r = jr; c = jc; dr = -dr; dc = -dc; }
            int di = (dr == 0) ? dc : (7 + (dr-1)*13 + dc + 6);
            sTab[e] = di | (r<<7) | (c<<10) | (ir<<13) | (ic<<16) | (jr<<19) | (jc<<22);
        }
    }
    // Stage bias projections, transposed [e][pos]  (2464 = 9*256 + 160)
    #pragma unroll
    for (int it = 0; it < 10; it++) {
        int i = it*256 + tid;
        if (i < 2464) {
            int e = i & 15, p2 = i >> 4;
            int r = p2 / 22, cpos = p2 % 22;
            sABt[e*161 + p2] = g_AB[(long)(bbase + (h+r)*54 + w0 + cpos)*16 + e];
        }
    }
    __syncthreads();

    float wacc0 = 0.f, wacc1 = 0.f, wacc2 = 0.f, wacc3 = 0.f;
    int px_b = tid >> 4, tg = tid & 15;

    for (int chk = 0; chk < 7; chk++) {
        int ii0 = chk*7;
        // B1: scores for 7 rows x 49 x 16 px  (5488 = 21*256 + 112)
        #pragma unroll
        for (int it = 0; it < 21; it++) {
            int f = it*256 + tid;
            int px = f & 15, q = f >> 4;
            int jj = q % 49, rr = q / 49;
            int t = sTab[(ii0+rr)*49 + jj];
            int di = t & 127, r = (t>>7)&7, c = (t>>10)&7;
            int ir = (t>>13)&7, ic = (t>>16)&7, jr = (t>>19)&7, jc = (t>>22)&7;
            int jpos = jr*22 + jc + px;
            float s = g_CORR[di*NP2 + bbase + (h+r)*54 + w0 + c + px]
                    + sABt[ir*161 + jpos]
                    + sABt[(8+ic)*161 + jpos];
            sS[(rr*49 + jj)*17 + px] = s;
        }
        if (tid < 112) {
            int f = 21*256 + tid;
            int px = f & 15, q = f >> 4;
            int jj = q % 49, rr = q / 49;
            int t = sTab[(ii0+rr)*49 + jj];
            int di = t & 127, r = (t>>7)&7, c = (t>>10)&7;
            int ir = (t>>13)&7, ic = (t>>16)&7, jr = (t>>19)&7, jc = (t>>22)&7;
            int jpos = jr*22 + jc + px;
            float s = g_CORR[di*NP2 + bbase + (h+r)*54 + w0 + c + px]
                    + sABt[ir*161 + jpos]
                    + sABt[(8+ic)*161 + jpos];
            sS[(rr*49 + jj)*17 + px] = s;
        }
        __syncthreads();
        // B2: row softmax (width-16 shfl) + accumulate column sums
        #pragma unroll
        for (int rr = 0; rr < 7; rr++) {
            float v0 = sS[(rr*49 + tg     )*17 + px_b];
            float v1 = sS[(rr*49 + tg + 16)*17 + px_b];
            float v2 = sS[(rr*49 + tg + 32)*17 + px_b];
            float v3 = (tg == 0) ? sS[(rr*49 + 48)*17 + px_b] : -1e30f;
            float m = fmaxf(fmaxf(v0, v1), fmaxf(v2, v3));
            #pragma unroll
            for (int o = 8; o; o >>= 1) m = fmaxf(m, __shfl_xor_sync(0xffffffffu, m, o, 16));
            float e0 = __expf(v0 - m), e1 = __expf(v1 - m), e2 = __expf(v2 - m);
            float e3 = (tg == 0) ? __expf(v3 - m) : 0.f;
            float s = e0 + e1 + e2 + e3;
            #pragma unroll
            for (int o = 8; o; o >>= 1) s += __shfl_xor_sync(0xffffffffu, s, o, 16);
            float inv = 1.f / s;
            wacc0 += e0*inv; wacc1 += e1*inv; wacc2 += e2*inv; wacc3 += e3*inv;
        }
        __syncthreads();
    }
    sWv[(tg     )*17 + px_b] = wacc0 * (1.f/49.f);
    sWv[(tg + 16)*17 + px_b] = wacc1 * (1.f/49.f);
    sWv[(tg + 32)*17 + px_b] = wacc2 * (1.f/49.f);
    if (tg == 0) sWv[48*17 + px_b] = wacc3 * (1.f/49.f);
    __syncthreads();

    // Phase C: V gather via smem staging, 64-channel chunks
    int px = tid & 15, tc = tid >> 4;
    for (int cc = 0; cc < 256; cc += 64) {
        #pragma unroll
        for (int it = 0; it < 10; it++) {
            int i = it*256 + tid;
            if (i < 2464) {
                int f4 = i & 15, p2 = i >> 4;
                int r = p2 / 22, cpos = p2 % 22;
                float4 v = *(const float4*)&g_V[(long)(bbase + (h+r)*54 + w0 + cpos)*256 + cc + f4*4];
                *(float4*)&sV[p2*68 + f4*4] = v;
            }
        }
        __syncthreads();
        float4 acc = make_float4(0.f, 0.f, 0.f, 0.f);
        #pragma unroll
        for (int jj = 0; jj < 49; jj++) {
            int jr = jj/7, jc = jj%7;
            float w = sWv[jj*17 + px];
            float4 v = *(const float4*)&sV[(jr*22 + jc + px)*68 + tc*4];
            acc.x += w*v.x; acc.y += w*v.y; acc.z += w*v.z; acc.w += w*v.w;
        }
        int ob = ((b*256 + cc + tc*4)*48 + h)*48 + w0 + px;
        out[ob]        = acc.x;
        out[ob + 2304] = acc.y;
        out[ob + 4608] = acc.z;
        out[ob + 6912] = acc.w;
        __syncthreads();
    }
}

// ---------------------------------------------------------------------------
extern "C" void kernel_launch(void* const* d_in, const int* in_sizes, int n_in,
                              void* d_out, int out_size) {
    const float* x    = (const float*)d_in[0];
    const float* wk   = (const float*)d_in[1];
    const float* wv   = (const float*)d_in[2];
    const float* relh = (const float*)d_in[3];
    const float* relw = (const float*)d_in[4];
    float* out = (float*)d_out;

    kGemmZ<<<dim3(36, 5), 256>>>(x, wk, wv);
    kCorr<<<dim3(7, 14, 2), 256>>>();
    kAB<<<729, 256>>>(relh, relw);
    kAttn<<<dim3(3, 48, 2), 256>>>(out);
}